// round 6
// baseline (speedup 1.0000x reference)
#include <cuda_runtime.h>

#define BB 16
#define NN 1024
#define DD 1024   // D2H
#define UU 512
#define TOK (BB * NN)

#define DGRP 4                      // d-groups of 256
#define UCH  32                     // u-chunks
#define UC   (UU / UCH)             // 16 u per chunk
#define PRO  (DGRP * UCH)           // 128 partial blocks
#define RED  4                      // reduce blocks (256 d each)
#define PRE  (PRO + RED + 1)        // +1 const block = 133
#define ROW_BLOCKS (TOK / 8)        // 2048
#define OUT_BLOCKS (TOK / 8)        // 2048
#define RB_PER_BATCH (NN / 8)       // 128
#define VREADY_TARGET (RED + 1)     // 4 reduce + 1 const

// Scratch (no device allocation allowed; counters zeroed by k_zero each launch).
__device__ float g_ph[UCH * DD];
__device__ float g_pm[UCH * DD];
__device__ float g_vh[DD];
__device__ float g_vm[DD];
__device__ float g_const;
__device__ float g_sH[TOK];
__device__ float g_sM[TOK];
__device__ int   g_c_pro;
__device__ int   g_c_v;
__device__ int   g_done[BB];

__global__ void k_zero() {
    int t = threadIdx.x;
    if (t < BB) g_done[t] = 0;
    if (t == BB)     g_c_pro = 0;
    if (t == BB + 1) g_c_v   = 0;
}

// ---------------------------------------------------------------------------
// Mega-kernel: bid-ordered pipeline (pro -> reduce/const -> row -> out).
// Row blocks prefetch their x tiles into registers BEFORE waiting on v, so
// the 64 MB x stream hides the whole v-precompute.
// ---------------------------------------------------------------------------
__global__ void __launch_bounds__(256, 4)
k_mega(const float* __restrict__ x, float* __restrict__ out,
       const float* __restrict__ Wh, const float* __restrict__ Wm,
       const float* __restrict__ bh, const float* __restrict__ bm,
       const float* __restrict__ wout, const float* __restrict__ bout) {
    int bid = blockIdx.x;
    int t   = threadIdx.x;

    if (bid < PRO) {
        // ---- v partials: 256 d's, 16 u's per block ----
        int d  = (bid & (DGRP - 1)) * 256 + t;
        int uc = bid >> 2;                    // / DGRP
        int u0 = uc * UC;
        float ah = 0.f, am = 0.f;
#pragma unroll
        for (int i = 0; i < UC; ++i) {
            float w = __ldg(&wout[u0 + i]);
            ah = fmaf(Wh[(size_t)(u0 + i) * DD + d], w, ah);
            am = fmaf(Wm[(size_t)(u0 + i) * DD + d], w, am);
        }
        g_ph[uc * DD + d] = ah;
        g_pm[uc * DD + d] = am;
        __threadfence();
        __syncthreads();
        if (t == 0) atomicAdd(&g_c_pro, 1);

    } else if (bid < PRO + RED) {
        // ---- fold 32 partials into v (256 d per block) ----
        if (t == 0) {
            while (*(volatile int*)&g_c_pro < PRO) __nanosleep(64);
            __threadfence();
        }
        __syncthreads();
        int d = (bid - PRO) * 256 + t;
        float ah = 0.f, am = 0.f;
#pragma unroll
        for (int c = 0; c < UCH; ++c) {
            ah += g_ph[c * DD + d];
            am += g_pm[c * DD + d];
        }
        g_vh[d] = ah;
        g_vm[d] = am;
        __threadfence();
        __syncthreads();
        if (t == 0) atomicAdd(&g_c_v, 1);

    } else if (bid < PRE) {
        // ---- const block: g_const = (b_h+b_m).w_out + b_out ----
        __shared__ float red[8];
        float acc = (bh[t] + bm[t]) * wout[t]
                  + (bh[t + 256] + bm[t + 256]) * wout[t + 256];
#pragma unroll
        for (int o = 16; o > 0; o >>= 1)
            acc += __shfl_down_sync(0xffffffffu, acc, o);
        if ((t & 31) == 0) red[t >> 5] = acc;
        __syncthreads();
        if (t < 8) {
            acc = red[t];
#pragma unroll
            for (int o = 4; o > 0; o >>= 1)
                acc += __shfl_down_sync(0x000000ffu, acc, o);
            if (t == 0) {
                g_const = acc + bout[0];
                __threadfence();
                atomicAdd(&g_c_v, 1);
            }
        }

    } else if (bid < PRE + ROW_BLOCKS) {
        // ---- row blocks: prefetch x, wait for v, dual dot, publish ----
        int rb   = bid - PRE;
        int row  = rb * 8 + (t >> 5);
        int lane = t & 31;
        const float4* xr  = reinterpret_cast<const float4*>(x + (size_t)row * DD);
        const float4* vh4 = reinterpret_cast<const float4*>(g_vh);
        const float4* vm4 = reinterpret_cast<const float4*>(g_vm);

        float4 xv[8];
#pragma unroll
        for (int i = 0; i < 8; ++i)
            xv[i] = __ldcs(&xr[lane + 32 * i]);   // in flight during the wait

        if (t == 0) {
            while (*(volatile int*)&g_c_v < VREADY_TARGET) __nanosleep(64);
            __threadfence();
        }
        __syncthreads();

        float ah = 0.f, am = 0.f;
#pragma unroll
        for (int i = 0; i < 8; ++i) {
            int idx = lane + 32 * i;
            float4 h = vh4[idx];
            float4 m = vm4[idx];
            ah = fmaf(xv[i].x, h.x, fmaf(xv[i].y, h.y, fmaf(xv[i].z, h.z, fmaf(xv[i].w, h.w, ah))));
            am = fmaf(xv[i].x, m.x, fmaf(xv[i].y, m.y, fmaf(xv[i].z, m.z, fmaf(xv[i].w, m.w, am))));
        }
#pragma unroll
        for (int o = 16; o > 0; o >>= 1) {
            ah += __shfl_xor_sync(0xffffffffu, ah, o);
            am += __shfl_xor_sync(0xffffffffu, am, o);
        }
        if (lane == 0) {
            g_sH[row] = ah;
            g_sM[row] = am;
            __threadfence();
        }
        __syncthreads();
        if (t == 0) atomicAdd(&g_done[rb >> 7], 1);   // RB_PER_BATCH = 128

    } else {
        // ---- out blocks: wait for own batch, write 8 rows (__stcs) ----
        int ob = bid - PRE - ROW_BLOCKS;
        int i0 = ob * 8;
        int b  = i0 >> 10;

        if (t == 0) {
            while (*(volatile int*)&g_done[b] < RB_PER_BATCH) __nanosleep(128);
            __threadfence();
        }
        __syncthreads();

        float4 m = reinterpret_cast<const float4*>(g_sM + (size_t)b * NN)[t];
        float  c = g_const;
        float4 h0 = reinterpret_cast<const float4*>(g_sH + i0)[0];
        float4 h1 = reinterpret_cast<const float4*>(g_sH + i0)[1];
        float base[8] = {h0.x + c, h0.y + c, h0.z + c, h0.w + c,
                         h1.x + c, h1.y + c, h1.z + c, h1.w + c};
#pragma unroll
        for (int r = 0; r < 8; ++r) {
            __stcs(reinterpret_cast<float4*>(out + (size_t)(i0 + r) * NN) + t,
                   make_float4(base[r] + m.x, base[r] + m.y,
                               base[r] + m.z, base[r] + m.w));
        }
    }
}

extern "C" void kernel_launch(void* const* d_in, const int* in_sizes, int n_in,
                              void* d_out, int out_size) {
    const float* x    = (const float*)d_in[0];
    const float* Wh   = (const float*)d_in[1];
    const float* bh   = (const float*)d_in[2];
    const float* Wm   = (const float*)d_in[3];
    const float* bm   = (const float*)d_in[4];
    const float* wout = (const float*)d_in[5];
    const float* bout = (const float*)d_in[6];
    float* out = (float*)d_out;

    k_zero<<<1, 32>>>();
    k_mega<<<PRE + ROW_BLOCKS + OUT_BLOCKS, 256>>>(x, out, Wh, Wm, bh, bm, wout, bout);
}

// round 7
// speedup vs baseline: 1.1130x; 1.1130x over previous
#include <cuda_runtime.h>

#define BB 16
#define NN 1024
#define DD 1024   // D2H
#define UU 512
#define TOK (BB * NN)

#define DGRP 4                      // d-groups of 256
#define UCH  32                     // u-chunks
#define UC   (UU / UCH)             // 16 u per chunk
#define PRO  (DGRP * UCH)           // 128 prologue blocks
#define ROW_BLOCKS (TOK / 8)        // 2048 (8 rows per block, warp per row)
#define OUT_BLOCKS (TOK / 8)        // 2048
#define RB_PER_BATCH (NN / 8)       // 128

// Scratch (no device allocation allowed; rewritten every launch).
__device__ float g_ph[UCH * DD];
__device__ float g_pm[UCH * DD];
__device__ float g_vh[DD];
__device__ float g_vm[DD];
__device__ float g_const;
__device__ float g_sH[TOK];
__device__ float g_sM[TOK];
__device__ int   g_done[BB];

// ---------------------------------------------------------------------------
// Stage 1: v partials with REAL parallelism: 128 blocks x 256 threads,
// 16 u's per thread (32 independent strided loads in flight).
// Block 0 also zeroes the g_done counters for this replay.
// ---------------------------------------------------------------------------
__global__ void k_pre(const float* __restrict__ Wh,
                      const float* __restrict__ Wm,
                      const float* __restrict__ wout) {
    int t = threadIdx.x;
    if (blockIdx.x == 0 && t < BB) g_done[t] = 0;

    int d  = (blockIdx.x & (DGRP - 1)) * 256 + t;
    int uc = blockIdx.x >> 2;               // / DGRP, 0..31
    int u0 = uc * UC;
    float ah = 0.f, am = 0.f;
#pragma unroll
    for (int i = 0; i < UC; ++i) {
        float w = __ldg(&wout[u0 + i]);
        ah = fmaf(Wh[(size_t)(u0 + i) * DD + d], w, ah);
        am = fmaf(Wm[(size_t)(u0 + i) * DD + d], w, am);
    }
    g_ph[uc * DD + d] = ah;
    g_pm[uc * DD + d] = am;
}

// ---------------------------------------------------------------------------
// Stage 2: blocks 0..3 fold the 32 partials into v_h/v_m (256 d each);
// block 4 computes g_const = (b_h + b_m) . w_out + b_out.
// ---------------------------------------------------------------------------
__global__ void k_finish(const float* __restrict__ bh,
                         const float* __restrict__ bm,
                         const float* __restrict__ wout,
                         const float* __restrict__ bout) {
    int t = threadIdx.x;
    if (blockIdx.x < 4) {
        int d = blockIdx.x * 256 + t;
        float ah = 0.f, am = 0.f;
#pragma unroll
        for (int c = 0; c < UCH; ++c) {
            ah += g_ph[c * DD + d];
            am += g_pm[c * DD + d];
        }
        g_vh[d] = ah;
        g_vm[d] = am;
    } else {
        __shared__ float red[8];
        float acc = (bh[t] + bm[t]) * wout[t]
                  + (bh[t + 256] + bm[t + 256]) * wout[t + 256];
#pragma unroll
        for (int o = 16; o > 0; o >>= 1)
            acc += __shfl_down_sync(0xffffffffu, acc, o);
        if ((t & 31) == 0) red[t >> 5] = acc;
        __syncthreads();
        if (t < 8) {
            acc = red[t];
#pragma unroll
            for (int o = 4; o > 0; o >>= 1)
                acc += __shfl_down_sync(0x000000ffu, acc, o);
            if (t == 0) g_const = acc + bout[0];
        }
    }
}

// ---------------------------------------------------------------------------
// Stage 3 (fused row+out pipeline) — identical to the proven R4 kernel.
// ---------------------------------------------------------------------------
__global__ void __launch_bounds__(256, 4)
k_main(const float* __restrict__ x, float* __restrict__ out) {
    int bid = blockIdx.x;
    int t   = threadIdx.x;

    if (bid < ROW_BLOCKS) {
        // ---- producer: dual dot products for 8 rows, warp per row ----
        int row  = bid * 8 + (t >> 5);
        int lane = t & 31;
        const float4* xr  = reinterpret_cast<const float4*>(x + (size_t)row * DD);
        const float4* vh4 = reinterpret_cast<const float4*>(g_vh);
        const float4* vm4 = reinterpret_cast<const float4*>(g_vm);

        float4 xv[8];
#pragma unroll
        for (int i = 0; i < 8; ++i)
            xv[i] = __ldcs(&xr[lane + 32 * i]);     // 8 independent LDG.128.CS

        float ah = 0.f, am = 0.f;
#pragma unroll
        for (int i = 0; i < 8; ++i) {
            int idx = lane + 32 * i;
            float4 h = vh4[idx];
            float4 m = vm4[idx];
            ah = fmaf(xv[i].x, h.x, fmaf(xv[i].y, h.y, fmaf(xv[i].z, h.z, fmaf(xv[i].w, h.w, ah))));
            am = fmaf(xv[i].x, m.x, fmaf(xv[i].y, m.y, fmaf(xv[i].z, m.z, fmaf(xv[i].w, m.w, am))));
        }
#pragma unroll
        for (int o = 16; o > 0; o >>= 1) {
            ah += __shfl_xor_sync(0xffffffffu, ah, o);
            am += __shfl_xor_sync(0xffffffffu, am, o);
        }
        if (lane == 0) {
            g_sH[row] = ah;
            g_sM[row] = am;
            __threadfence();                        // release own stores
        }
        __syncthreads();
        if (t == 0) atomicAdd(&g_done[bid >> 7], 1);   // RB_PER_BATCH = 128
    } else {
        // ---- consumer: write 8 output rows of one batch ----
        int ob = bid - ROW_BLOCKS;
        int i0 = ob * 8;            // global row base (b*NN + i)
        int b  = i0 >> 10;          // NN = 1024

        if (t == 0) {
            while (*(volatile int*)&g_done[b] < RB_PER_BATCH)
                __nanosleep(128);
            __threadfence();        // acquire
        }
        __syncthreads();

        float4 m = reinterpret_cast<const float4*>(g_sM + (size_t)b * NN)[t];
        float  c = g_const;
        float4 h0 = reinterpret_cast<const float4*>(g_sH + i0)[0];
        float4 h1 = reinterpret_cast<const float4*>(g_sH + i0)[1];
        float base[8] = {h0.x + c, h0.y + c, h0.z + c, h0.w + c,
                         h1.x + c, h1.y + c, h1.z + c, h1.w + c};
#pragma unroll
        for (int r = 0; r < 8; ++r) {
            __stcs(reinterpret_cast<float4*>(out + (size_t)(i0 + r) * NN) + t,
                   make_float4(base[r] + m.x, base[r] + m.y,
                               base[r] + m.z, base[r] + m.w));
        }
    }
}

extern "C" void kernel_launch(void* const* d_in, const int* in_sizes, int n_in,
                              void* d_out, int out_size) {
    const float* x    = (const float*)d_in[0];
    const float* Wh   = (const float*)d_in[1];
    const float* bh   = (const float*)d_in[2];
    const float* Wm   = (const float*)d_in[3];
    const float* bm   = (const float*)d_in[4];
    const float* wout = (const float*)d_in[5];
    const float* bout = (const float*)d_in[6];
    float* out = (float*)d_out;

    k_pre<<<PRO, 256>>>(Wh, Wm, wout);
    k_finish<<<5, 256>>>(bh, bm, wout, bout);
    k_main<<<ROW_BLOCKS + OUT_BLOCKS, 256>>>(x, out);
}